// round 1
// baseline (speedup 1.0000x reference)
#include <cuda_runtime.h>

typedef unsigned long long u64;

// Pack two f32 into a b64 register (maps to MOV.64 pair; ALU pipe, dual-issues with FMA).
__device__ __forceinline__ u64 pk2(float lo, float hi) {
    u64 r;
    asm("mov.b64 %0, {%1, %2};" : "=l"(r)
        : "r"(__float_as_uint(lo)), "r"(__float_as_uint(hi)));
    return r;
}
// Packed dual FMA: d.lo = a.lo*b.lo + c.lo ; d.hi = a.hi*b.hi + c.hi  (FFMA2 on sm_103a)
__device__ __forceinline__ u64 ffma2(u64 a, u64 b, u64 c) {
    u64 d;
    asm("fma.rn.f32x2 %0, %1, %2, %3;" : "=l"(d) : "l"(a), "l"(b), "l"(c));
    return d;
}
__device__ __forceinline__ float f2lo(u64 v) { return __uint_as_float((unsigned)v); }
__device__ __forceinline__ float f2hi(u64 v) { return __uint_as_float((unsigned)(v >> 32)); }

// x: [B,1,7,7,7,7]  w1: [2,1,3,3,3,3]  b1:[2]  w2: [4,2,3,3,3,3]  b2:[4]
// out: [B, 4*81]  (oc,l,d,h,w flattened)
__global__ __launch_bounds__(256)
void fused4d_kernel(const float* __restrict__ x,
                    const float* __restrict__ w1, const float* __restrict__ b1,
                    const float* __restrict__ w2, const float* __restrict__ b2,
                    float* __restrict__ out, int nsamp)
{
    __shared__ float  xs[2][2401];     // per-sample input tile
    __shared__ float  h1s[2][1250];    // per-sample hidden: [c][5^4]
    __shared__ float2 w1p[81];         // (oc0, oc1) per tap
    __shared__ float2 w2p[4][81];      // per oc: (ic0, ic1) per tap
    __shared__ float2 b1p;
    __shared__ float  b2s[4];

    const int t  = threadIdx.x;
    const int s0 = blockIdx.x * 2;

    // ---- weights -> smem (pre-paired for f32x2) ----
    for (int i = t; i < 81; i += 256)
        w1p[i] = make_float2(w1[i], w1[81 + i]);
    for (int i = t; i < 324; i += 256) {
        int oc = i / 81, tap = i - oc * 81;
        w2p[oc][tap] = make_float2(w2[oc * 162 + tap], w2[oc * 162 + 81 + tap]);
    }
    if (t == 0) b1p = make_float2(b1[0], b1[1]);
    if (t < 4)  b2s[t] = b2[t];

    // ---- input -> smem (both samples, coalesced) ----
    {
        const float* xb = x + (size_t)s0 * 2401;
        int lim = (s0 + 1 < nsamp) ? 4802 : 2401;
        for (int i = t; i < lim; i += 256) ((float*)xs)[i] = xb[i];
    }
    __syncthreads();

    const int s    = t >> 7;        // sample within block
    const int tid  = t & 127;
    const int samp = s0 + s;
    const bool active = (samp < nsamp);

    // ================= layer 1 =================
    // thread = (l,d,h) in 5^3; computes both channels x 5 w-positions.
    // f32x2 lanes = (oc0, oc1).
    if (active && tid < 125) {
        const int l = tid / 25, d = (tid / 5) % 5, h = tid % 5;
        const float* xb = &xs[s][0] + l * 343 + d * 49 + h * 7;
        const u64 bb = *(const u64*)&b1p;
        u64 acc[5];
        #pragma unroll
        for (int p = 0; p < 5; p++) acc[p] = bb;

        #pragma unroll
        for (int i = 0; i < 3; i++)
        #pragma unroll
        for (int j = 0; j < 3; j++)
        #pragma unroll
        for (int k = 0; k < 3; k++) {
            const float* r = xb + i * 343 + j * 49 + k * 7;
            u64 xx[7];
            #pragma unroll
            for (int q = 0; q < 7; q++) { float v = r[q]; xx[q] = pk2(v, v); }
            const u64* wp = (const u64*)&w1p[((i * 3 + j) * 3 + k) * 3];
            #pragma unroll
            for (int m = 0; m < 3; m++) {
                const u64 w = wp[m];               // broadcast LDS.64
                #pragma unroll
                for (int p = 0; p < 5; p++)
                    acc[p] = ffma2(xx[p + m], w, acc[p]);
            }
        }
        float* hb = &h1s[s][0] + ((l * 5 + d) * 5 + h) * 5;
        #pragma unroll
        for (int p = 0; p < 5; p++) {
            hb[p]       = fmaxf(f2lo(acc[p]), 0.f);   // ch0
            hb[625 + p] = fmaxf(f2hi(acc[p]), 0.f);   // ch1
        }
    }
    __syncthreads();

    // ================= layer 2 =================
    // thread = (l,d,h) in 3^3; computes all 4 oc x 3 w-positions.
    // f32x2 lanes = (ic0 partial, ic1 partial); summed at epilogue.
    if (active && tid < 27) {
        const int l = tid / 9, d = (tid / 3) % 3, h = tid % 3;
        const float* hb0 = &h1s[s][0] + l * 125 + d * 25 + h * 5;

        u64 acc[4][3];
        #pragma unroll
        for (int oc = 0; oc < 4; oc++) {
            u64 ini = pk2(b2s[oc], 0.f);
            #pragma unroll
            for (int p = 0; p < 3; p++) acc[oc][p] = ini;
        }

        #pragma unroll
        for (int i = 0; i < 3; i++)
        #pragma unroll
        for (int j = 0; j < 3; j++)
        #pragma unroll
        for (int k = 0; k < 3; k++) {
            const float* r = hb0 + i * 125 + j * 25 + k * 5;
            u64 hh[5];
            #pragma unroll
            for (int q = 0; q < 5; q++) hh[q] = pk2(r[q], r[625 + q]);
            const int tb = ((i * 3 + j) * 3 + k) * 3;
            #pragma unroll
            for (int m = 0; m < 3; m++) {
                #pragma unroll
                for (int oc = 0; oc < 4; oc++) {
                    const u64 w = *(const u64*)&w2p[oc][tb + m];  // broadcast LDS.64
                    #pragma unroll
                    for (int p = 0; p < 3; p++)
                        acc[oc][p] = ffma2(hh[p + m], w, acc[oc][p]);
                }
            }
        }

        float* ob = out + (size_t)samp * 324;
        const int pb = ((l * 3 + d) * 3 + h) * 3;
        #pragma unroll
        for (int oc = 0; oc < 4; oc++)
        #pragma unroll
        for (int p = 0; p < 3; p++)
            ob[oc * 81 + pb + p] =
                fmaxf(f2lo(acc[oc][p]) + f2hi(acc[oc][p]), 0.f);
    }
}

extern "C" void kernel_launch(void* const* d_in, const int* in_sizes, int n_in,
                              void* d_out, int out_size) {
    const float* x  = (const float*)d_in[0];
    const float* w1 = (const float*)d_in[1];
    const float* b1 = (const float*)d_in[2];
    const float* w2 = (const float*)d_in[3];
    const float* b2 = (const float*)d_in[4];
    float* out = (float*)d_out;

    const int n = in_sizes[0] / 2401;          // B = 16384
    const int blocks = (n + 1) / 2;            // 2 samples per block
    fused4d_kernel<<<blocks, 256>>>(x, w1, b1, w2, b2, out, n);
}

// round 2
// speedup vs baseline: 1.2080x; 1.2080x over previous
#include <cuda_runtime.h>

typedef unsigned long long u64;

__device__ __forceinline__ u64 pk2(float lo, float hi) {
    u64 r;
    asm("mov.b64 %0, {%1, %2};" : "=l"(r)
        : "r"(__float_as_uint(lo)), "r"(__float_as_uint(hi)));
    return r;
}
__device__ __forceinline__ u64 ffma2(u64 a, u64 b, u64 c) {
    u64 d;
    asm("fma.rn.f32x2 %0, %1, %2, %3;" : "=l"(d) : "l"(a), "l"(b), "l"(c));
    return d;
}
__device__ __forceinline__ float f2lo(u64 v) { return __uint_as_float((unsigned)v); }
__device__ __forceinline__ float f2hi(u64 v) { return __uint_as_float((unsigned)(v >> 32)); }

// x: [B,1,7,7,7,7]  w1:[2,1,3,3,3,3] b1:[2]  w2:[4,2,3,3,3,3] b2:[4]
// out: [B, 4*81]
__global__ __launch_bounds__(256)
void fused4d_kernel(const float* __restrict__ x,
                    const float* __restrict__ w1, const float* __restrict__ b1,
                    const float* __restrict__ w2, const float* __restrict__ b2,
                    float* __restrict__ out, int nsamp)
{
    __shared__ float  xs[3][2401];
    __shared__ float  h1s[3][1250];     // [s][c][5^4]
    __shared__ float2 w1p[81];          // (oc0,oc1) per tap
    __shared__ float2 w2p[4][81];       // per oc: (ic0,ic1) per tap
    __shared__ float2 b1p;
    __shared__ float  b2s[4];

    const int t  = threadIdx.x;
    const int s0 = blockIdx.x * 3;

    for (int i = t; i < 81; i += 256)
        w1p[i] = make_float2(w1[i], w1[81 + i]);
    for (int i = t; i < 324; i += 256) {
        int oc = i / 81, tap = i - oc * 81;
        w2p[oc][tap] = make_float2(w2[oc * 162 + tap], w2[oc * 162 + 81 + tap]);
    }
    if (t == 0) b1p = make_float2(b1[0], b1[1]);
    if (t < 4)  b2s[t] = b2[t];

    {
        int nsm = nsamp - s0; if (nsm > 3) nsm = 3;
        int lim = nsm * 2401;
        const float* xb = x + (size_t)s0 * 2401;
        for (int i = t; i < lim; i += 256) ((float*)xs)[i] = xb[i];
    }
    __syncthreads();

    // ================= layer 1 =================
    // 75 threads/sample: (l,d,hpair); each computes 2h x 5w outputs, both channels
    // packed in f32x2 lanes (oc0,oc1).
    if (t < 225 && s0 + t / 75 < nsamp) {
        const int s   = t / 75;
        const int tid = t % 75;
        const int l   = tid / 15;
        const int d   = (tid % 15) / 3;
        const int hp  = tid % 3;
        const int h0  = 2 * hp;                 // outputs h0, h0+1 (h0=4: 2nd discarded)

        const float* xbase = &xs[s][0] + l * 343 + d * 49;
        const u64 bb = *(const u64*)&b1p;
        u64 acc[2][5];
        #pragma unroll
        for (int hh = 0; hh < 2; hh++)
            #pragma unroll
            for (int p = 0; p < 5; p++) acc[hh][p] = bb;

        #pragma unroll
        for (int i = 0; i < 3; i++)
        #pragma unroll
        for (int j = 0; j < 3; j++) {
            const float* rbase = xbase + i * 343 + j * 49;
            // 9 weights for this (i,j) into registers
            u64 wr[9];
            const u64* wp = (const u64*)&w1p[(i * 3 + j) * 9];
            #pragma unroll
            for (int q = 0; q < 9; q++) wr[q] = wp[q];

            #pragma unroll
            for (int rr = 0; rr < 4; rr++) {
                int r = h0 + rr; if (r > 6) r = 6;   // clamp only touches discarded acc
                const float* rp = rbase + r * 7;
                u64 xx[7];
                #pragma unroll
                for (int q = 0; q < 7; q++) { float v = rp[q]; xx[q] = pk2(v, v); }
                #pragma unroll
                for (int m = 0; m < 3; m++) {
                    if (rr <= 2) {            // (hh=0, k=rr)
                        const u64 w = wr[rr * 3 + m];
                        #pragma unroll
                        for (int p = 0; p < 5; p++)
                            acc[0][p] = ffma2(xx[p + m], w, acc[0][p]);
                    }
                    if (rr >= 1) {            // (hh=1, k=rr-1)
                        const u64 w = wr[(rr - 1) * 3 + m];
                        #pragma unroll
                        for (int p = 0; p < 5; p++)
                            acc[1][p] = ffma2(xx[p + m], w, acc[1][p]);
                    }
                }
            }
        }

        float* hb = &h1s[s][0];
        #pragma unroll
        for (int hh = 0; hh < 2; hh++) {
            int h = h0 + hh;
            if (h < 5) {
                int base = ((l * 5 + d) * 5 + h) * 5;
                #pragma unroll
                for (int p = 0; p < 5; p++) {
                    hb[base + p]       = fmaxf(f2lo(acc[hh][p]), 0.f);
                    hb[625 + base + p] = fmaxf(f2hi(acc[hh][p]), 0.f);
                }
            }
        }
    }
    __syncthreads();

    // ================= layer 2 =================
    // 54 threads/sample: (pos in 3^3) x (oc-pair). Adjacent lanes share hh
    // addresses (broadcast). f32x2 lanes = (ic0,ic1) partials.
    if (t < 162 && s0 + t / 54 < nsamp) {
        const int s    = t / 54;
        const int tid  = t % 54;
        const int ocp  = tid & 1;
        const int pos  = tid >> 1;
        const int l = pos / 9, d = (pos / 3) % 3, h = pos % 3;
        const int oc0  = 2 * ocp;

        const float* hb0 = &h1s[s][0] + l * 125 + d * 25 + h * 5;

        u64 acc[2][3];
        #pragma unroll
        for (int cc = 0; cc < 2; cc++) {
            u64 ini = pk2(b2s[oc0 + cc], 0.f);
            #pragma unroll
            for (int p = 0; p < 3; p++) acc[cc][p] = ini;
        }

        #pragma unroll
        for (int i = 0; i < 3; i++)
        #pragma unroll
        for (int j = 0; j < 3; j++)
        #pragma unroll
        for (int k = 0; k < 3; k++) {
            const float* r = hb0 + i * 125 + j * 25 + k * 5;
            u64 hh_[5];
            #pragma unroll
            for (int q = 0; q < 5; q++) hh_[q] = pk2(r[q], r[625 + q]);
            const int tb = ((i * 3 + j) * 3 + k) * 3;
            #pragma unroll
            for (int m = 0; m < 3; m++) {
                #pragma unroll
                for (int cc = 0; cc < 2; cc++) {
                    const u64 w = *(const u64*)&w2p[oc0 + cc][tb + m];
                    #pragma unroll
                    for (int p = 0; p < 3; p++)
                        acc[cc][p] = ffma2(hh_[p + m], w, acc[cc][p]);
                }
            }
        }

        float* ob = out + (size_t)(s0 + s) * 324;
        const int pb = ((l * 3 + d) * 3 + h) * 3;
        #pragma unroll
        for (int cc = 0; cc < 2; cc++)
        #pragma unroll
        for (int p = 0; p < 3; p++)
            ob[(oc0 + cc) * 81 + pb + p] =
                fmaxf(f2lo(acc[cc][p]) + f2hi(acc[cc][p]), 0.f);
    }
}

extern "C" void kernel_launch(void* const* d_in, const int* in_sizes, int n_in,
                              void* d_out, int out_size) {
    const float* x  = (const float*)d_in[0];
    const float* w1 = (const float*)d_in[1];
    const float* b1 = (const float*)d_in[2];
    const float* w2 = (const float*)d_in[3];
    const float* b2 = (const float*)d_in[4];
    float* out = (float*)d_out;

    const int n = in_sizes[0] / 2401;          // B
    const int blocks = (n + 2) / 3;            // 3 samples per block
    fused4d_kernel<<<blocks, 256>>>(x, w1, b1, w2, b2, out, n);
}